// round 15
// baseline (speedup 1.0000x reference)
#include <cuda_runtime.h>

#define BB 64
#define N1 201
#define DD 128
#define HF 100
#define MM (BB*N1)          // 12864
#define NEGV -1e20f
#define NT2B 101            // t2 blocks per batch (ceil(201/2))

typedef unsigned long long ull;

// ---------------- scratch ----------------
__device__ __align__(16) float g_gv[BB*DD];
__device__ __align__(16) float g_hhat[MM*DD];        // 6.6 MB
__device__ __align__(16) float g_M[4*DD*DD];         // WQ_h @ WK_h^T (removal)
__device__ __align__(16) float g_proj[4*MM*DD];      // P = hhat @ M_h (26 MB)
__device__ __align__(16) float g_qt[16*BB*DD];       // folded qtilde vectors
__device__ __align__(16) float g_feat[BB*HF*8];      // removal compat features
__device__ __align__(16) int2  g_idx[BB*200];        // (ipre, ipost) per item
__device__ __align__(16) float g_rc[MM*32];
__device__ __align__(16) float g_cc[MM*32];
__device__ int   g_a1[BB];
__device__ float g_ll1[BB];
__device__ ull   g_pkey[BB*NT2B];
__device__ float g_psum[BB*NT2B];

// ---------------- f32x2 helpers ----------------
__device__ __forceinline__ ull ffma2(ull a, ull b, ull c) {
    ull d;
    asm("fma.rn.f32x2 %0, %1, %2, %3;" : "=l"(d) : "l"(a), "l"(b), "l"(c));
    return d;
}
__device__ __forceinline__ ull pack2(float x) {
    ull r;
    asm("mov.b64 %0, {%1, %2};" : "=l"(r) : "f"(x), "f"(x));
    return r;
}
__device__ __forceinline__ ull pack2v(float lo, float hi) {
    ull r;
    asm("mov.b64 %0, {%1, %2};" : "=l"(r) : "f"(lo), "f"(hi));
    return r;
}
__device__ __forceinline__ void unpack2(ull v, float& lo, float& hi) {
    asm("mov.b64 {%0, %1}, %2;" : "=f"(lo), "=f"(hi) : "l"(v));
}

// ---------------- K1: prep (0..63) + mmat (64..575) + idx (576..639) ----------------
__global__ __launch_bounds__(128) void k_prep_mmat(const float* __restrict__ hw,
                                                   const float* __restrict__ Wg,
                                                   const float* __restrict__ WQ,
                                                   const float* __restrict__ WK,
                                                   const int* __restrict__ sol_g) {
    int bid = blockIdx.x;
    int tid = threadIdx.x;
    if (bid < BB) {
        __shared__ float hm[DD];
        int b = bid;
        const float* p = hw + (size_t)b*N1*DD + tid;
        float m = -3.4e38f;
        for (int n = 0; n < N1; n++) m = fmaxf(m, p[n*DD]);
        hm[tid] = m;
        __syncthreads();
        float s = 0.f;
        for (int k = 0; k < DD; k++) s += hm[k] * Wg[k*DD + tid];
        g_gv[b*DD + tid] = s;
    } else if (bid < BB + 4*DD) {
        __shared__ float wk[DD];
        int x = bid - BB;
        int h = x >> 7, dp = x & 127;
        wk[tid] = WK[(size_t)(h*DD + dp)*DD + tid];
        __syncthreads();
        const float4* q4 = (const float4*)(WQ + (size_t)(h*DD + tid)*DD);
        const float4* k4 = (const float4*)wk;
        float s = 0.f;
        #pragma unroll
        for (int c = 0; c < 32; c++) {
            float4 a = q4[c], bq = k4[c];
            s += a.x*bq.x + a.y*bq.y + a.z*bq.z + a.w*bq.w;
        }
        g_M[(size_t)(h*DD + tid)*DD + dp] = s;
    } else {
        __shared__ int sol[N1], inv[N1];
        int b = bid - (BB + 4*DD);
        for (int i = tid; i < N1; i += 128) sol[i] = sol_g[b*N1 + i];
        __syncthreads();
        for (int i = tid; i < N1; i += 128) inv[sol[i]] = i;
        __syncthreads();
        for (int item = tid; item < 200; item += 128) {
            int n = item + 1;
            g_idx[b*200 + item] = make_int2(inv[n], sol[sol[n]]);
        }
    }
}

// ---------------- K2: h_hat = h_wave @ Wn + g[b] — f32x2, 16 rows/block ----------------
__global__ __launch_bounds__(128) void k_hhat(const float* __restrict__ hw,
                                              const float* __restrict__ Wn) {
    __shared__ float Asf[DD][18];
    int r0 = blockIdx.x * 16;
    int tid = threadIdx.x;
    #pragma unroll
    for (int rr = 0; rr < 16; rr++) {
        Asf[tid][(rr & 7)*2 + (rr >> 3)] = hw[(size_t)(r0+rr)*DD + tid];
    }
    __syncthreads();
    ull acc[8];
    #pragma unroll
    for (int p = 0; p < 8; p++) {
        int bl = (r0 + p) / N1, bh = (r0 + p + 8) / N1;
        acc[p] = pack2v(g_gv[bl*DD + tid], g_gv[bh*DD + tid]);
    }
    #pragma unroll 4
    for (int k = 0; k < DD; k++) {
        ull w2 = pack2(Wn[k*DD + tid]);
        const ull* arow = (const ull*)&Asf[k][0];
        #pragma unroll
        for (int p = 0; p < 8; p++) acc[p] = ffma2(arow[p], w2, acc[p]);
    }
    #pragma unroll
    for (int p = 0; p < 8; p++) {
        float lo, hi; unpack2(acc[p], lo, hi);
        g_hhat[(size_t)(r0+p)*DD + tid]   = lo;
        g_hhat[(size_t)(r0+p+8)*DD + tid] = hi;
    }
}

// ---------------- K4: P = hhat @ M — f32x2, 96x64 tile, B-resident + A double-buffer ----------------
__global__ __launch_bounds__(128) void k_pgemm() {
    __shared__ __align__(16) float Bs[DD][64];        // full 128x64 W slice: 32 KB
    __shared__ __align__(16) float As[2][16][98];     // A chunk double buffer
    int bm = blockIdx.x;              // 0..133 (134*96 = 12864 exact)
    int bn = blockIdx.y;              // 0..7
    int h  = bn >> 1;
    int d0 = (bn & 1) * 64;
    const float* W = g_M + (size_t)h * DD * DD;

    int tid = threadIdx.x;
    int tx = tid & 15, ty = tid >> 4;

    for (int l = tid; l < 2048; l += 128) {
        int row = l >> 4, c4 = (l & 15) * 4;
        *(float4*)&Bs[row][c4] = *(const float4*)(W + (size_t)row*DD + d0 + c4);
    }

    int arowv[3], ac4v[3];
    #pragma unroll
    for (int q = 0; q < 3; q++) {
        int idx = tid + 128*q;
        arowv[q] = idx >> 2;
        ac4v[q]  = (idx & 3) * 4;
    }

    float4 aR[3];
    #pragma unroll
    for (int q = 0; q < 3; q++)
        aR[q] = *(const float4*)(g_hhat + (size_t)(bm*96 + arowv[q])*DD + 0 + ac4v[q]);
    #pragma unroll
    for (int q = 0; q < 3; q++) {
        As[0][ac4v[q]+0][arowv[q]] = aR[q].x; As[0][ac4v[q]+1][arowv[q]] = aR[q].y;
        As[0][ac4v[q]+2][arowv[q]] = aR[q].z; As[0][ac4v[q]+3][arowv[q]] = aR[q].w;
    }
    __syncthreads();

    ull c2[6][4] = {};
    #pragma unroll 1
    for (int ch = 0; ch < 8; ch++) {
        int buf = ch & 1;
        if (ch < 7) {
            #pragma unroll
            for (int q = 0; q < 3; q++)
                aR[q] = *(const float4*)(g_hhat + (size_t)(bm*96 + arowv[q])*DD + (ch+1)*16 + ac4v[q]);
        }
        #pragma unroll
        for (int kk = 0; kk < 16; kk++) {
            const ull* ap = (const ull*)&As[buf][kk][ty*12];
            float4 bv = *(const float4*)&Bs[ch*16 + kk][tx*4];
            ull b0 = pack2(bv.x), b1 = pack2(bv.y), b2 = pack2(bv.z), b3 = pack2(bv.w);
            #pragma unroll
            for (int p = 0; p < 6; p++) {
                ull a2 = ap[p];
                c2[p][0] = ffma2(a2, b0, c2[p][0]);
                c2[p][1] = ffma2(a2, b1, c2[p][1]);
                c2[p][2] = ffma2(a2, b2, c2[p][2]);
                c2[p][3] = ffma2(a2, b3, c2[p][3]);
            }
        }
        if (ch < 7) {
            #pragma unroll
            for (int q = 0; q < 3; q++) {
                As[buf^1][ac4v[q]+0][arowv[q]] = aR[q].x; As[buf^1][ac4v[q]+1][arowv[q]] = aR[q].y;
                As[buf^1][ac4v[q]+2][arowv[q]] = aR[q].z; As[buf^1][ac4v[q]+3][arowv[q]] = aR[q].w;
            }
        }
        __syncthreads();
    }

    float* out = g_proj + (size_t)h * MM * DD;
    int row0 = bm*96 + ty*12, col0 = d0 + tx*4;
    #pragma unroll
    for (int p = 0; p < 6; p++) {
        float l0,h0,l1,h1,l2,h2,l3,h3;
        unpack2(c2[p][0], l0, h0); unpack2(c2[p][1], l1, h1);
        unpack2(c2[p][2], l2, h2); unpack2(c2[p][3], l3, h3);
        float4 v0; v0.x=l0; v0.y=l1; v0.z=l2; v0.w=l3;
        float4 v1; v1.x=h0; v1.y=h1; v1.z=h2; v1.w=h3;
        *(float4*)(out + (size_t)(row0 + 2*p + 0)*DD + col0) = v0;
        *(float4*)(out + (size_t)(row0 + 2*p + 1)*DD + col0) = v1;
    }
}

// ---------------- K5a: removal compat dots — warp-per-item, no smem ----------------
__global__ __launch_bounds__(256) void k_t1a() {
    int w = blockIdx.x * 8 + (threadIdx.x >> 5);   // 0..12799
    int lane = threadIdx.x & 31;
    int b = w / 200, item = w % 200;
    int2 ix = g_idx[b*200 + item];
    int n = item + 1;
    int half = (item < HF) ? 0 : 1;
    int m = (item < HF) ? item : (item - HF);

    float4 xn = ((const float4*)(g_hhat + (size_t)(b*N1 + n   )*DD))[lane];
    float4 xp = ((const float4*)(g_hhat + (size_t)(b*N1 + ix.y)*DD))[lane];
    float4 pp4[4], pn4[4];
    #pragma unroll
    for (int h = 0; h < 4; h++) {
        pp4[h] = ((const float4*)(g_proj + ((size_t)h*MM + b*N1 + ix.x)*DD))[lane];
        pn4[h] = ((const float4*)(g_proj + ((size_t)h*MM + b*N1 + n   )*DD))[lane];
    }
    float sh[4];
    #pragma unroll
    for (int h = 0; h < 4; h++) {
        float4 pp = pp4[h], pn = pn4[h];
        float s = pp.x*xn.x + pp.y*xn.y + pp.z*xn.z + pp.w*xn.w
                + pn.x*xp.x + pn.y*xp.y + pn.z*xp.z + pn.w*xp.w
                - (pp.x*xp.x + pp.y*xp.y + pp.z*xp.z + pp.w*xp.w);
        #pragma unroll
        for (int off = 16; off > 0; off >>= 1) s += __shfl_xor_sync(0xFFFFFFFF, s, off);
        sh[h] = s;
    }
    if (lane == 0) {
        float4 v; v.x = sh[0]; v.y = sh[1]; v.z = sh[2]; v.w = sh[3];
        *(float4*)(g_feat + ((size_t)b*HF + m)*8 + half*4) = v;
    }
}

// ---------------- K5b: removal MLP + softmax/argmax ----------------
__global__ __launch_bounds__(128) void k_t1b(const float* __restrict__ selrec,
                     const int* __restrict__ pre_action,
                     const float* __restrict__ w1, const float* __restrict__ b1,
                     const float* __restrict__ w2, const float* __restrict__ b2,
                     const float* __restrict__ w3, const float* __restrict__ b3) {
    __shared__ float t1s[HF];
    __shared__ float W1[12*32], B1[32], W2s[32*32], B2s[32], W3s[32];
    int b = blockIdx.x, tid = threadIdx.x;
    for (int i = tid; i < 12*32; i += 128) W1[i] = w1[i];
    for (int i = tid; i < 32*32; i += 128) W2s[i] = w2[i];
    if (tid < 32) { B1[tid] = b1[tid]; B2s[tid] = b2[tid]; W3s[tid] = w3[tid]; }
    __syncthreads();

    if (tid < HF) {
        int m = tid;
        float feat[12];
        #pragma unroll
        for (int c = 0; c < 8; c++) feat[c] = g_feat[((size_t)b*HF + m)*8 + c];
        #pragma unroll
        for (int s = 0; s < 4; s++) feat[8+s] = selrec[b*4*HF + s*HF + m];
        float h1[32];
        #pragma unroll
        for (int c = 0; c < 32; c++) {
            float s = B1[c];
            #pragma unroll
            for (int f = 0; f < 12; f++) s += feat[f] * W1[f*32 + c];
            h1[c] = fmaxf(s, 0.f);
        }
        float h2[32];
        #pragma unroll
        for (int c = 0; c < 32; c++) {
            float s = B2s[c];
            #pragma unroll
            for (int f = 0; f < 32; f++) s += h1[f] * W2s[f*32 + c];
            h2[c] = fmaxf(s, 0.f);
        }
        float o = b3[0];
        #pragma unroll
        for (int c = 0; c < 32; c++) o += h2[c] * W3s[c];
        float t1 = tanhf(o) * 6.0f;
        if (pre_action[0] > 0 && m == pre_action[b*2]) t1 = NEGV;
        t1s[m] = t1;
    }
    __syncthreads();
    if (tid == 0) {
        float mx = t1s[0]; int am = 0;
        for (int m = 1; m < HF; m++) if (t1s[m] > mx) { mx = t1s[m]; am = m; }
        float se = 0.f;
        for (int m = 0; m < HF; m++) se += __expf(t1s[m] - mx);
        g_a1[b] = am;
        g_ll1[b] = -__logf(se);
    }
}

// ---------------- K6: qtilde — weights amortized over 8 batches ----------------
__global__ __launch_bounds__(128) void k_qt(const float* __restrict__ i1q, const float* __restrict__ i1k,
                                            const float* __restrict__ i2q, const float* __restrict__ i2k) {
    __shared__ float hp[8][DD];
    __shared__ float u[8][DD];
    __shared__ float Ws[16][DD+2];
    int x = blockIdx.x;               // 0..15: t*4+h
    int t = x >> 2, h = x & 3;
    int b0 = blockIdx.y * 8;
    int tid = threadIdx.x;
    const float* Wq = ((t & 1) ? i2q : i1q) + (size_t)h*DD*DD;
    const float* Wk = ((t & 1) ? i2k : i1k) + (size_t)h*DD*DD;

    #pragma unroll
    for (int bb = 0; bb < 8; bb++) {
        int b = b0 + bb;
        int a1 = g_a1[b];
        int pos = (t < 2) ? (1 + a1) : (1 + HF + a1);
        hp[bb][tid] = g_hhat[(size_t)(b*N1 + pos)*DD + tid];
    }
    __syncthreads();
    {
        float acc[8] = {};
        for (int k = 0; k < DD; k++) {
            float w = Wq[(size_t)k*DD + tid];
            #pragma unroll
            for (int bb = 0; bb < 8; bb++) acc[bb] += hp[bb][k] * w;
        }
        #pragma unroll
        for (int bb = 0; bb < 8; bb++) u[bb][tid] = acc[bb];
    }
    __syncthreads();
    float q[8] = {};
    for (int e0 = 0; e0 < DD; e0 += 16) {
        #pragma unroll
        for (int qq = 0; qq < 16; qq++) {
            int l = tid + 128*qq;
            int dd = l >> 4, ee = l & 15;
            Ws[ee][dd] = Wk[(size_t)dd*DD + e0 + ee];
        }
        __syncthreads();
        #pragma unroll
        for (int ee = 0; ee < 16; ee++) {
            float w = Ws[ee][tid];
            #pragma unroll
            for (int bb = 0; bb < 8; bb++) q[bb] += u[bb][e0+ee] * w;
        }
        __syncthreads();
    }
    #pragma unroll
    for (int bb = 0; bb < 8; bb++)
        g_qt[((size_t)x*BB + b0 + bb)*DD + tid] = q[bb];
}

// ---------------- K7: row/col layer-1 — smem-staged, coalesced ----------------
__global__ __launch_bounds__(128) void k_rc(const int* __restrict__ sol_g,
                                            const float* __restrict__ w1, const float* __restrict__ b1v) {
    __shared__ __align__(16) float qv[16*DD];        // 8 KB
    __shared__ __align__(16) float xi[32][132];
    __shared__ __align__(16) float xs[32][132];
    __shared__ float sdots[32][17];
    __shared__ float W1[16*32], B1[32];
    __shared__ int   soli[32];
    int b = blockIdx.y;
    int i0 = blockIdx.x * 32;        // 7*32 = 224 >= 201
    int tid = threadIdx.x;
    int wid = tid >> 5, lane = tid & 31;

    {
        const float4* src = (const float4*)(g_qt);
        float4* dst = (float4*)qv;
        for (int l = tid; l < 16*DD/4; l += 128) {
            int x = l >> 5, q = l & 31;
            dst[l] = src[((size_t)x*BB + b)*32 + q];
        }
    }
    for (int l = tid; l < 16*32; l += 128) W1[l] = w1[l];
    if (tid < 32) B1[tid] = b1v[tid];
    if (tid < 32) soli[tid] = (i0 + tid < N1) ? sol_g[b*N1 + i0 + tid] : 0;
    __syncthreads();

    {
        const float4* src = (const float4*)(g_hhat + (size_t)(b*N1 + i0)*DD);
        int nrows = min(32, N1 - i0);
        for (int l = tid; l < nrows*32; l += 128) {
            int row = l >> 5, c = l & 31;
            float4 v = src[(size_t)row*32 + c];
            *(float4*)&xi[row][c*4] = v;
        }
    }
    for (int row = wid; row < 32; row += 4) {
        if (i0 + row < N1) {
            const float4* src = (const float4*)(g_hhat + (size_t)(b*N1 + soli[row])*DD);
            *(float4*)&xs[row][lane*4] = src[lane];
        }
    }
    __syncthreads();

    int il = tid & 31, h = tid >> 5;
    float s0 = 0.f, s1 = 0.f, s2 = 0.f, s3 = 0.f;
    {
        const float4* q0 = (const float4*)(qv + (0*4+h)*DD);
        const float4* q1 = (const float4*)(qv + (1*4+h)*DD);
        const float4* q2 = (const float4*)(qv + (2*4+h)*DD);
        const float4* q3 = (const float4*)(qv + (3*4+h)*DD);
        #pragma unroll 8
        for (int c = 0; c < 32; c++) {
            float4 vi = *(const float4*)&xi[il][c*4];
            float4 vs = *(const float4*)&xs[il][c*4];
            float4 a0 = q0[c], a1 = q1[c], a2 = q2[c], a3 = q3[c];
            s0 += a0.x*vi.x + a0.y*vi.y + a0.z*vi.z + a0.w*vi.w;
            s1 += a1.x*vs.x + a1.y*vs.y + a1.z*vs.z + a1.w*vs.w;
            s2 += a2.x*vi.x + a2.y*vi.y + a2.z*vi.z + a2.w*vi.w;
            s3 += a3.x*vs.x + a3.y*vs.y + a3.z*vs.z + a3.w*vs.w;
        }
    }
    const float invs = 0.08838834764831845f;  // 1/sqrt(128)
    sdots[il][h]      = s0*invs;
    sdots[il][4+h]    = s1*invs;
    sdots[il][8+h]    = s2*invs;
    sdots[il][12+h]   = s3*invs;
    __syncthreads();

    int cg = tid >> 5;
    int i = i0 + il;
    if (i < N1) {
        float f[16];
        #pragma unroll
        for (int k = 0; k < 16; k++) f[k] = sdots[il][k];
        float rs[8], cs[8];
        #pragma unroll
        for (int cc = 0; cc < 8; cc++) {
            int c = cg*8 + cc;
            float r = 0.f, s = B1[c];
            #pragma unroll
            for (int k = 0; k < 8; k++) {
                r += f[k]     * W1[k*32 + c];
                s += f[8+k]   * W1[(8+k)*32 + c];
            }
            rs[cc] = r; cs[cc] = s;
        }
        float* rdst = g_rc + (size_t)(b*N1 + i)*32 + cg*8;
        float* cdst = g_cc + (size_t)(b*N1 + i)*32 + cg*8;
        #pragma unroll
        for (int q = 0; q < 2; q++) {
            float4 v; v.x = rs[q*4]; v.y = rs[q*4+1]; v.z = rs[q*4+2]; v.w = rs[q*4+3];
            *(float4*)(rdst + q*4) = v;
            float4 w; w.x = cs[q*4]; w.y = cs[q*4+1]; w.z = cs[q*4+2]; w.w = cs[q*4+3];
            *(float4*)(cdst + q*4) = w;
        }
    }
}

// ---------------- K8: fused reinsertion MLP + in-block reduction — f32x2, 224 threads ----------------
__global__ __launch_bounds__(224, 1) void k_t2(const unsigned char* __restrict__ maskt,
                                               const float* __restrict__ w2, const float* __restrict__ b2,
                                               const float* __restrict__ w3, const float* __restrict__ b3) {
    __shared__ __align__(16) float W2[32*32];
    __shared__ __align__(8)  float B2[32];
    __shared__ float W3[32];
    __shared__ float rc0[32], rc1[32];
    __shared__ float cjs[N1*33];
    __shared__ ull   skw[7];
    __shared__ float ssw[7];
    __shared__ float B3;
    int b = blockIdx.y;
    int i0 = blockIdx.x * 2;
    int tid = threadIdx.x;
    int wid = tid >> 5, lane = tid & 31;
    for (int l = tid; l < 256; l += 224) {
        float4 v = ((const float4*)w2)[l];
        int kk = l >> 3, q = l & 7;
        W2[kk*32 + q*4 + 0] = v.x; W2[kk*32 + q*4 + 1] = v.y;
        W2[kk*32 + q*4 + 2] = v.z; W2[kk*32 + q*4 + 3] = v.w;
    }
    if (tid < 32) { B2[tid] = b2[tid]; W3[tid] = w3[tid]; }
    if (tid == 0) B3 = b3[0];
    if (tid < 32)      rc0[tid]    = g_rc[(size_t)(b*N1 + i0)*32 + tid];
    else if (tid < 64) rc1[tid-32] = (i0+1 < N1) ? g_rc[(size_t)(b*N1 + i0 + 1)*32 + (tid-32)] : 0.f;
    {
        const float4* ccb = (const float4*)(g_cc + (size_t)b*N1*32);
        for (int l = tid; l < N1*8; l += 224) {
            int j = l >> 3, q = l & 7;
            float4 v = ccb[l];
            cjs[j*33 + q*4 + 0] = v.x; cjs[j*33 + q*4 + 1] = v.y;
            cjs[j*33 + q*4 + 2] = v.z; cjs[j*33 + q*4 + 3] = v.w;
        }
    }
    __syncthreads();

    ull bk = 0; float bs = 0.f;
    int j = tid;
    if (j < N1) {
        const ull* B2d = (const ull*)B2;
        const float* cj = cjs + j*33;
        ull acc0[16], acc1[16];
        #pragma unroll
        for (int q = 0; q < 16; q++) { acc0[q] = B2d[q]; acc1[q] = B2d[q]; }
        #pragma unroll 4
        for (int kk = 0; kk < 32; kk++) {
            float cjk = cj[kk];
            ull hh0 = pack2(fmaxf(rc0[kk] + cjk, 0.f));
            ull hh1 = pack2(fmaxf(rc1[kk] + cjk, 0.f));
            const ulonglong2* wr = (const ulonglong2*)(W2 + kk*32);
            #pragma unroll
            for (int q = 0; q < 8; q++) {
                ulonglong2 w = wr[q];
                acc0[2*q]   = ffma2(hh0, w.x, acc0[2*q]);
                acc0[2*q+1] = ffma2(hh0, w.y, acc0[2*q+1]);
                acc1[2*q]   = ffma2(hh1, w.x, acc1[2*q]);
                acc1[2*q+1] = ffma2(hh1, w.y, acc1[2*q+1]);
            }
        }
        {
            int i = i0;
            float o = B3;
            #pragma unroll
            for (int q = 0; q < 16; q++) {
                float lo, hi;
                unpack2(acc0[q], lo, hi);
                o += fmaxf(lo, 0.f) * W3[2*q] + fmaxf(hi, 0.f) * W3[2*q+1];
            }
            float t2v = maskt[((size_t)b*N1 + i)*N1 + j] ? NEGV : tanhf(o)*6.0f;
            unsigned int lin = (unsigned int)(i*N1 + j);
            unsigned int u = __float_as_uint(t2v);
            unsigned int ord = (u >> 31) ? ~u : (u | 0x80000000u);
            ull key = ((ull)ord << 32) | (0xFFFFFFFFu - lin);
            if (key > bk) bk = key;
            bs += __expf(t2v - 6.f);
        }
        if (i0 + 1 < N1) {
            int i = i0 + 1;
            float o = B3;
            #pragma unroll
            for (int q = 0; q < 16; q++) {
                float lo, hi;
                unpack2(acc1[q], lo, hi);
                o += fmaxf(lo, 0.f) * W3[2*q] + fmaxf(hi, 0.f) * W3[2*q+1];
            }
            float t2v = maskt[((size_t)b*N1 + i)*N1 + j] ? NEGV : tanhf(o)*6.0f;
            unsigned int lin = (unsigned int)(i*N1 + j);
            unsigned int u = __float_as_uint(t2v);
            unsigned int ord = (u >> 31) ? ~u : (u | 0x80000000u);
            ull key = ((ull)ord << 32) | (0xFFFFFFFFu - lin);
            if (key > bk) bk = key;
            bs += __expf(t2v - 6.f);
        }
    }
    #pragma unroll
    for (int off = 16; off > 0; off >>= 1) {
        ull ok = __shfl_xor_sync(0xFFFFFFFF, bk, off);
        float os = __shfl_xor_sync(0xFFFFFFFF, bs, off);
        if (ok > bk) bk = ok;
        bs += os;
    }
    if (lane == 0) { skw[wid] = bk; ssw[wid] = bs; }
    __syncthreads();
    if (tid == 0) {
        ull k = skw[0]; float s = ssw[0];
        #pragma unroll
        for (int w = 1; w < 7; w++) {
            if (skw[w] > k) k = skw[w];
            s += ssw[w];
        }
        g_pkey[b*NT2B + blockIdx.x] = k;
        g_psum[b*NT2B + blockIdx.x] = s;
    }
}

// ---------------- K9: final per-batch reduce (deterministic) ----------------
__global__ void k_red(float* __restrict__ out) {
    int b = threadIdx.x;
    if (b < BB) {
        ull bk = 0; float s = 0.f;
        for (int p = 0; p < NT2B; p++) {
            ull k = g_pkey[b*NT2B + p];
            if (k > bk) bk = k;
            s += g_psum[b*NT2B + p];
        }
        unsigned int ord = (unsigned int)(bk >> 32);
        unsigned int u = (ord & 0x80000000u) ? (ord ^ 0x80000000u) : ~ord;
        float vmax = __uint_as_float(u);
        unsigned int lin = 0xFFFFFFFFu - (unsigned int)(bk & 0xFFFFFFFFu);
        float ll2 = vmax - 6.f - __logf(s);
        out[b*3 + 0] = (float)g_a1[b];
        out[b*3 + 1] = (float)(lin / N1);
        out[b*3 + 2] = (float)(lin % N1);
        out[BB*3 + b] = g_ll1[b] + ll2;
    }
}

// ---------------- launch ----------------
extern "C" void kernel_launch(void* const* d_in, const int* in_sizes, int n_in,
                              void* d_out, int out_size) {
    const float* h_wave      = (const float*)d_in[0];
    const int*   solution    = (const int*)d_in[1];
    const float* selrec      = (const float*)d_in[2];
    const int*   pre_action  = (const int*)d_in[3];
    const unsigned char* mt  = (const unsigned char*)d_in[4];
    const float* Wn  = (const float*)d_in[5];
    const float* Wg  = (const float*)d_in[6];
    const float* rmWQ = (const float*)d_in[7];
    const float* rmWK = (const float*)d_in[8];
    const float* rw1 = (const float*)d_in[9];
    const float* rb1 = (const float*)d_in[10];
    const float* rw2 = (const float*)d_in[11];
    const float* rb2 = (const float*)d_in[12];
    const float* rw3 = (const float*)d_in[13];
    const float* rb3 = (const float*)d_in[14];
    const float* i1q = (const float*)d_in[15];
    const float* i1k = (const float*)d_in[16];
    const float* i2q = (const float*)d_in[17];
    const float* i2k = (const float*)d_in[18];
    const float* ew1 = (const float*)d_in[19];
    const float* eb1 = (const float*)d_in[20];
    const float* ew2 = (const float*)d_in[21];
    const float* eb2 = (const float*)d_in[22];
    const float* ew3 = (const float*)d_in[23];
    const float* eb3 = (const float*)d_in[24];
    float* out = (float*)d_out;

    k_prep_mmat<<<BB + 4*DD + BB, DD>>>(h_wave, Wg, rmWQ, rmWK, solution);
    k_hhat<<<MM/16, DD>>>(h_wave, Wn);
    {
        dim3 gg(134, 8);
        k_pgemm<<<gg, 128>>>();
    }
    k_t1a<<<1600, 256>>>();
    k_t1b<<<BB, 128>>>(selrec, pre_action, rw1, rb1, rw2, rb2, rw3, rb3);
    {
        dim3 gq(16, 8);
        k_qt<<<gq, 128>>>(i1q, i1k, i2q, i2k);
    }
    {
        dim3 gr(7, BB);
        k_rc<<<gr, 128>>>(solution, ew1, eb1);
    }
    {
        dim3 gt(NT2B, BB);
        k_t2<<<gt, 224>>>(mt, ew2, eb2, ew3, eb3);
    }
    k_red<<<1, 64>>>(out);
}

// round 16
// speedup vs baseline: 1.0135x; 1.0135x over previous
#include <cuda_runtime.h>

#define BB 64
#define N1 201
#define DD 128
#define HF 100
#define MM (BB*N1)          // 12864
#define NEGV -1e20f
#define NT2B 101            // t2 blocks per batch (ceil(201/2))

typedef unsigned long long ull;

// ---------------- scratch ----------------
__device__ __align__(16) float g_gv[BB*DD];
__device__ __align__(16) float g_hhat[MM*DD];        // 6.6 MB
__device__ __align__(16) float g_M[4*DD*DD];         // WQ_h @ WK_h^T (removal)
__device__ __align__(16) float g_proj[4*MM*DD];      // P = hhat @ M_h (26 MB)
__device__ __align__(16) float g_qt[16*BB*DD];       // folded qtilde vectors
__device__ __align__(16) float g_feat[BB*HF*8];      // removal compat features
__device__ __align__(16) int2  g_idx[BB*200];        // (ipre, ipost) per item
__device__ __align__(16) float g_rc[MM*32];
__device__ __align__(16) float g_cc[MM*32];
__device__ int   g_a1[BB];
__device__ float g_ll1[BB];
__device__ ull   g_pkey[BB*NT2B];
__device__ float g_psum[BB*NT2B];

// ---------------- f32x2 helpers ----------------
__device__ __forceinline__ ull ffma2(ull a, ull b, ull c) {
    ull d;
    asm("fma.rn.f32x2 %0, %1, %2, %3;" : "=l"(d) : "l"(a), "l"(b), "l"(c));
    return d;
}
__device__ __forceinline__ ull pack2(float x) {
    ull r;
    asm("mov.b64 %0, {%1, %2};" : "=l"(r) : "f"(x), "f"(x));
    return r;
}
__device__ __forceinline__ ull pack2v(float lo, float hi) {
    ull r;
    asm("mov.b64 %0, {%1, %2};" : "=l"(r) : "f"(lo), "f"(hi));
    return r;
}
__device__ __forceinline__ void unpack2(ull v, float& lo, float& hi) {
    asm("mov.b64 {%0, %1}, %2;" : "=f"(lo), "=f"(hi) : "l"(v));
}

// ---------------- K1: prep (0..63) + mmat (64..575) + idx (576..639) ----------------
__global__ __launch_bounds__(128) void k_prep_mmat(const float* __restrict__ hw,
                                                   const float* __restrict__ Wg,
                                                   const float* __restrict__ WQ,
                                                   const float* __restrict__ WK,
                                                   const int* __restrict__ sol_g) {
    int bid = blockIdx.x;
    int tid = threadIdx.x;
    if (bid < BB) {
        __shared__ float hm[DD];
        int b = bid;
        const float* p = hw + (size_t)b*N1*DD + tid;
        float m = -3.4e38f;
        for (int n = 0; n < N1; n++) m = fmaxf(m, p[n*DD]);
        hm[tid] = m;
        __syncthreads();
        float s = 0.f;
        for (int k = 0; k < DD; k++) s += hm[k] * Wg[k*DD + tid];
        g_gv[b*DD + tid] = s;
    } else if (bid < BB + 4*DD) {
        __shared__ float wk[DD];
        int x = bid - BB;
        int h = x >> 7, dp = x & 127;
        wk[tid] = WK[(size_t)(h*DD + dp)*DD + tid];
        __syncthreads();
        const float4* q4 = (const float4*)(WQ + (size_t)(h*DD + tid)*DD);
        const float4* k4 = (const float4*)wk;
        float s = 0.f;
        #pragma unroll
        for (int c = 0; c < 32; c++) {
            float4 a = q4[c], bq = k4[c];
            s += a.x*bq.x + a.y*bq.y + a.z*bq.z + a.w*bq.w;
        }
        g_M[(size_t)(h*DD + tid)*DD + dp] = s;
    } else {
        __shared__ int sol[N1], inv[N1];
        int b = bid - (BB + 4*DD);
        for (int i = tid; i < N1; i += 128) sol[i] = sol_g[b*N1 + i];
        __syncthreads();
        for (int i = tid; i < N1; i += 128) inv[sol[i]] = i;
        __syncthreads();
        for (int item = tid; item < 200; item += 128) {
            int n = item + 1;
            g_idx[b*200 + item] = make_int2(inv[n], sol[sol[n]]);
        }
    }
}

// ---------------- K2: h_hat = h_wave @ Wn + g[b] — f32x2, 16 rows/block ----------------
__global__ __launch_bounds__(128) void k_hhat(const float* __restrict__ hw,
                                              const float* __restrict__ Wn) {
    __shared__ float Asf[DD][18];
    int r0 = blockIdx.x * 16;
    int tid = threadIdx.x;
    #pragma unroll
    for (int rr = 0; rr < 16; rr++) {
        Asf[tid][(rr & 7)*2 + (rr >> 3)] = hw[(size_t)(r0+rr)*DD + tid];
    }
    __syncthreads();
    ull acc[8];
    #pragma unroll
    for (int p = 0; p < 8; p++) {
        int bl = (r0 + p) / N1, bh = (r0 + p + 8) / N1;
        acc[p] = pack2v(g_gv[bl*DD + tid], g_gv[bh*DD + tid]);
    }
    #pragma unroll 4
    for (int k = 0; k < DD; k++) {
        ull w2 = pack2(Wn[k*DD + tid]);
        const ull* arow = (const ull*)&Asf[k][0];
        #pragma unroll
        for (int p = 0; p < 8; p++) acc[p] = ffma2(arow[p], w2, acc[p]);
    }
    #pragma unroll
    for (int p = 0; p < 8; p++) {
        float lo, hi; unpack2(acc[p], lo, hi);
        g_hhat[(size_t)(r0+p)*DD + tid]   = lo;
        g_hhat[(size_t)(r0+p+8)*DD + tid] = hi;
    }
}

// ---------------- K4: P = hhat @ M — f32x2, 96x64 tile, B-resident + A double-buffer ----------------
__global__ __launch_bounds__(128) void k_pgemm() {
    __shared__ __align__(16) float Bs[DD][64];        // full 128x64 W slice: 32 KB
    __shared__ __align__(16) float As[2][16][98];     // A chunk double buffer
    int bm = blockIdx.x;              // 0..133 (134*96 = 12864 exact)
    int bn = blockIdx.y;              // 0..7
    int h  = bn >> 1;
    int d0 = (bn & 1) * 64;
    const float* W = g_M + (size_t)h * DD * DD;

    int tid = threadIdx.x;
    int tx = tid & 15, ty = tid >> 4;

    for (int l = tid; l < 2048; l += 128) {
        int row = l >> 4, c4 = (l & 15) * 4;
        *(float4*)&Bs[row][c4] = *(const float4*)(W + (size_t)row*DD + d0 + c4);
    }

    int arowv[3], ac4v[3];
    #pragma unroll
    for (int q = 0; q < 3; q++) {
        int idx = tid + 128*q;
        arowv[q] = idx >> 2;
        ac4v[q]  = (idx & 3) * 4;
    }

    float4 aR[3];
    #pragma unroll
    for (int q = 0; q < 3; q++)
        aR[q] = *(const float4*)(g_hhat + (size_t)(bm*96 + arowv[q])*DD + 0 + ac4v[q]);
    #pragma unroll
    for (int q = 0; q < 3; q++) {
        As[0][ac4v[q]+0][arowv[q]] = aR[q].x; As[0][ac4v[q]+1][arowv[q]] = aR[q].y;
        As[0][ac4v[q]+2][arowv[q]] = aR[q].z; As[0][ac4v[q]+3][arowv[q]] = aR[q].w;
    }
    __syncthreads();

    ull c2[6][4] = {};
    #pragma unroll 1
    for (int ch = 0; ch < 8; ch++) {
        int buf = ch & 1;
        if (ch < 7) {
            #pragma unroll
            for (int q = 0; q < 3; q++)
                aR[q] = *(const float4*)(g_hhat + (size_t)(bm*96 + arowv[q])*DD + (ch+1)*16 + ac4v[q]);
        }
        #pragma unroll
        for (int kk = 0; kk < 16; kk++) {
            const ull* ap = (const ull*)&As[buf][kk][ty*12];
            float4 bv = *(const float4*)&Bs[ch*16 + kk][tx*4];
            ull b0 = pack2(bv.x), b1 = pack2(bv.y), b2 = pack2(bv.z), b3 = pack2(bv.w);
            #pragma unroll
            for (int p = 0; p < 6; p++) {
                ull a2 = ap[p];
                c2[p][0] = ffma2(a2, b0, c2[p][0]);
                c2[p][1] = ffma2(a2, b1, c2[p][1]);
                c2[p][2] = ffma2(a2, b2, c2[p][2]);
                c2[p][3] = ffma2(a2, b3, c2[p][3]);
            }
        }
        if (ch < 7) {
            #pragma unroll
            for (int q = 0; q < 3; q++) {
                As[buf^1][ac4v[q]+0][arowv[q]] = aR[q].x; As[buf^1][ac4v[q]+1][arowv[q]] = aR[q].y;
                As[buf^1][ac4v[q]+2][arowv[q]] = aR[q].z; As[buf^1][ac4v[q]+3][arowv[q]] = aR[q].w;
            }
        }
        __syncthreads();
    }

    float* out = g_proj + (size_t)h * MM * DD;
    int row0 = bm*96 + ty*12, col0 = d0 + tx*4;
    #pragma unroll
    for (int p = 0; p < 6; p++) {
        float l0,h0,l1,h1,l2,h2,l3,h3;
        unpack2(c2[p][0], l0, h0); unpack2(c2[p][1], l1, h1);
        unpack2(c2[p][2], l2, h2); unpack2(c2[p][3], l3, h3);
        float4 v0; v0.x=l0; v0.y=l1; v0.z=l2; v0.w=l3;
        float4 v1; v1.x=h0; v1.y=h1; v1.z=h2; v1.w=h3;
        *(float4*)(out + (size_t)(row0 + 2*p + 0)*DD + col0) = v0;
        *(float4*)(out + (size_t)(row0 + 2*p + 1)*DD + col0) = v1;
    }
}

// ---------------- K5a: removal compat dots — warp-per-item, no smem ----------------
__global__ __launch_bounds__(256) void k_t1a() {
    int w = blockIdx.x * 8 + (threadIdx.x >> 5);   // 0..12799
    int lane = threadIdx.x & 31;
    int b = w / 200, item = w % 200;
    int2 ix = g_idx[b*200 + item];
    int n = item + 1;
    int half = (item < HF) ? 0 : 1;
    int m = (item < HF) ? item : (item - HF);

    float4 xn = ((const float4*)(g_hhat + (size_t)(b*N1 + n   )*DD))[lane];
    float4 xp = ((const float4*)(g_hhat + (size_t)(b*N1 + ix.y)*DD))[lane];
    float4 pp4[4], pn4[4];
    #pragma unroll
    for (int h = 0; h < 4; h++) {
        pp4[h] = ((const float4*)(g_proj + ((size_t)h*MM + b*N1 + ix.x)*DD))[lane];
        pn4[h] = ((const float4*)(g_proj + ((size_t)h*MM + b*N1 + n   )*DD))[lane];
    }
    float sh[4];
    #pragma unroll
    for (int h = 0; h < 4; h++) {
        float4 pp = pp4[h], pn = pn4[h];
        float s = pp.x*xn.x + pp.y*xn.y + pp.z*xn.z + pp.w*xn.w
                + pn.x*xp.x + pn.y*xp.y + pn.z*xp.z + pn.w*xp.w
                - (pp.x*xp.x + pp.y*xp.y + pp.z*xp.z + pp.w*xp.w);
        #pragma unroll
        for (int off = 16; off > 0; off >>= 1) s += __shfl_xor_sync(0xFFFFFFFF, s, off);
        sh[h] = s;
    }
    if (lane == 0) {
        float4 v; v.x = sh[0]; v.y = sh[1]; v.z = sh[2]; v.w = sh[3];
        *(float4*)(g_feat + ((size_t)b*HF + m)*8 + half*4) = v;
    }
}

// ---------------- K5b: removal MLP + softmax/argmax ----------------
__global__ __launch_bounds__(128) void k_t1b(const float* __restrict__ selrec,
                     const int* __restrict__ pre_action,
                     const float* __restrict__ w1, const float* __restrict__ b1,
                     const float* __restrict__ w2, const float* __restrict__ b2,
                     const float* __restrict__ w3, const float* __restrict__ b3) {
    __shared__ float t1s[HF];
    __shared__ float W1[12*32], B1[32], W2s[32*32], B2s[32], W3s[32];
    int b = blockIdx.x, tid = threadIdx.x;
    for (int i = tid; i < 12*32; i += 128) W1[i] = w1[i];
    for (int i = tid; i < 32*32; i += 128) W2s[i] = w2[i];
    if (tid < 32) { B1[tid] = b1[tid]; B2s[tid] = b2[tid]; W3s[tid] = w3[tid]; }
    __syncthreads();

    if (tid < HF) {
        int m = tid;
        float feat[12];
        #pragma unroll
        for (int c = 0; c < 8; c++) feat[c] = g_feat[((size_t)b*HF + m)*8 + c];
        #pragma unroll
        for (int s = 0; s < 4; s++) feat[8+s] = selrec[b*4*HF + s*HF + m];
        float h1[32];
        #pragma unroll
        for (int c = 0; c < 32; c++) {
            float s = B1[c];
            #pragma unroll
            for (int f = 0; f < 12; f++) s += feat[f] * W1[f*32 + c];
            h1[c] = fmaxf(s, 0.f);
        }
        float h2[32];
        #pragma unroll
        for (int c = 0; c < 32; c++) {
            float s = B2s[c];
            #pragma unroll
            for (int f = 0; f < 32; f++) s += h1[f] * W2s[f*32 + c];
            h2[c] = fmaxf(s, 0.f);
        }
        float o = b3[0];
        #pragma unroll
        for (int c = 0; c < 32; c++) o += h2[c] * W3s[c];
        float t1 = tanhf(o) * 6.0f;
        if (pre_action[0] > 0 && m == pre_action[b*2]) t1 = NEGV;
        t1s[m] = t1;
    }
    __syncthreads();
    if (tid == 0) {
        float mx = t1s[0]; int am = 0;
        for (int m = 1; m < HF; m++) if (t1s[m] > mx) { mx = t1s[m]; am = m; }
        float se = 0.f;
        for (int m = 0; m < HF; m++) se += __expf(t1s[m] - mx);
        g_a1[b] = am;
        g_ll1[b] = -__logf(se);
    }
}

// ---------------- K6: qtilde — weights amortized over 8 batches ----------------
__global__ __launch_bounds__(128) void k_qt(const float* __restrict__ i1q, const float* __restrict__ i1k,
                                            const float* __restrict__ i2q, const float* __restrict__ i2k) {
    __shared__ float hp[8][DD];
    __shared__ float u[8][DD];
    __shared__ float Ws[16][DD+2];
    int x = blockIdx.x;               // 0..15: t*4+h
    int t = x >> 2, h = x & 3;
    int b0 = blockIdx.y * 8;
    int tid = threadIdx.x;
    const float* Wq = ((t & 1) ? i2q : i1q) + (size_t)h*DD*DD;
    const float* Wk = ((t & 1) ? i2k : i1k) + (size_t)h*DD*DD;

    #pragma unroll
    for (int bb = 0; bb < 8; bb++) {
        int b = b0 + bb;
        int a1 = g_a1[b];
        int pos = (t < 2) ? (1 + a1) : (1 + HF + a1);
        hp[bb][tid] = g_hhat[(size_t)(b*N1 + pos)*DD + tid];
    }
    __syncthreads();
    {
        float acc[8] = {};
        for (int k = 0; k < DD; k++) {
            float w = Wq[(size_t)k*DD + tid];
            #pragma unroll
            for (int bb = 0; bb < 8; bb++) acc[bb] += hp[bb][k] * w;
        }
        #pragma unroll
        for (int bb = 0; bb < 8; bb++) u[bb][tid] = acc[bb];
    }
    __syncthreads();
    float q[8] = {};
    for (int e0 = 0; e0 < DD; e0 += 16) {
        #pragma unroll
        for (int qq = 0; qq < 16; qq++) {
            int l = tid + 128*qq;
            int dd = l >> 4, ee = l & 15;
            Ws[ee][dd] = Wk[(size_t)dd*DD + e0 + ee];
        }
        __syncthreads();
        #pragma unroll
        for (int ee = 0; ee < 16; ee++) {
            float w = Ws[ee][tid];
            #pragma unroll
            for (int bb = 0; bb < 8; bb++) q[bb] += u[bb][e0+ee] * w;
        }
        __syncthreads();
    }
    #pragma unroll
    for (int bb = 0; bb < 8; bb++)
        g_qt[((size_t)x*BB + b0 + bb)*DD + tid] = q[bb];
}

// ---------------- K7: row/col layer-1 — smem-staged, coalesced ----------------
__global__ __launch_bounds__(128) void k_rc(const int* __restrict__ sol_g,
                                            const float* __restrict__ w1, const float* __restrict__ b1v) {
    __shared__ __align__(16) float qv[16*DD];        // 8 KB
    __shared__ __align__(16) float xi[32][132];
    __shared__ __align__(16) float xs[32][132];
    __shared__ float sdots[32][17];
    __shared__ float W1[16*32], B1[32];
    __shared__ int   soli[32];
    int b = blockIdx.y;
    int i0 = blockIdx.x * 32;        // 7*32 = 224 >= 201
    int tid = threadIdx.x;
    int wid = tid >> 5, lane = tid & 31;

    {
        const float4* src = (const float4*)(g_qt);
        float4* dst = (float4*)qv;
        for (int l = tid; l < 16*DD/4; l += 128) {
            int x = l >> 5, q = l & 31;
            dst[l] = src[((size_t)x*BB + b)*32 + q];
        }
    }
    for (int l = tid; l < 16*32; l += 128) W1[l] = w1[l];
    if (tid < 32) B1[tid] = b1v[tid];
    if (tid < 32) soli[tid] = (i0 + tid < N1) ? sol_g[b*N1 + i0 + tid] : 0;
    __syncthreads();

    {
        const float4* src = (const float4*)(g_hhat + (size_t)(b*N1 + i0)*DD);
        int nrows = min(32, N1 - i0);
        for (int l = tid; l < nrows*32; l += 128) {
            int row = l >> 5, c = l & 31;
            float4 v = src[(size_t)row*32 + c];
            *(float4*)&xi[row][c*4] = v;
        }
    }
    for (int row = wid; row < 32; row += 4) {
        if (i0 + row < N1) {
            const float4* src = (const float4*)(g_hhat + (size_t)(b*N1 + soli[row])*DD);
            *(float4*)&xs[row][lane*4] = src[lane];
        }
    }
    __syncthreads();

    int il = tid & 31, h = tid >> 5;
    float s0 = 0.f, s1 = 0.f, s2 = 0.f, s3 = 0.f;
    {
        const float4* q0 = (const float4*)(qv + (0*4+h)*DD);
        const float4* q1 = (const float4*)(qv + (1*4+h)*DD);
        const float4* q2 = (const float4*)(qv + (2*4+h)*DD);
        const float4* q3 = (const float4*)(qv + (3*4+h)*DD);
        #pragma unroll 8
        for (int c = 0; c < 32; c++) {
            float4 vi = *(const float4*)&xi[il][c*4];
            float4 vs = *(const float4*)&xs[il][c*4];
            float4 a0 = q0[c], a1 = q1[c], a2 = q2[c], a3 = q3[c];
            s0 += a0.x*vi.x + a0.y*vi.y + a0.z*vi.z + a0.w*vi.w;
            s1 += a1.x*vs.x + a1.y*vs.y + a1.z*vs.z + a1.w*vs.w;
            s2 += a2.x*vi.x + a2.y*vi.y + a2.z*vi.z + a2.w*vi.w;
            s3 += a3.x*vs.x + a3.y*vs.y + a3.z*vs.z + a3.w*vs.w;
        }
    }
    const float invs = 0.08838834764831845f;  // 1/sqrt(128)
    sdots[il][h]      = s0*invs;
    sdots[il][4+h]    = s1*invs;
    sdots[il][8+h]    = s2*invs;
    sdots[il][12+h]   = s3*invs;
    __syncthreads();

    int cg = tid >> 5;
    int i = i0 + il;
    if (i < N1) {
        float f[16];
        #pragma unroll
        for (int k = 0; k < 16; k++) f[k] = sdots[il][k];
        float rs[8], cs[8];
        #pragma unroll
        for (int cc = 0; cc < 8; cc++) {
            int c = cg*8 + cc;
            float r = 0.f, s = B1[c];
            #pragma unroll
            for (int k = 0; k < 8; k++) {
                r += f[k]     * W1[k*32 + c];
                s += f[8+k]   * W1[(8+k)*32 + c];
            }
            rs[cc] = r; cs[cc] = s;
        }
        float* rdst = g_rc + (size_t)(b*N1 + i)*32 + cg*8;
        float* cdst = g_cc + (size_t)(b*N1 + i)*32 + cg*8;
        #pragma unroll
        for (int q = 0; q < 2; q++) {
            float4 v; v.x = rs[q*4]; v.y = rs[q*4+1]; v.z = rs[q*4+2]; v.w = rs[q*4+3];
            *(float4*)(rdst + q*4) = v;
            float4 w; w.x = cs[q*4]; w.y = cs[q*4+1]; w.z = cs[q*4+2]; w.w = cs[q*4+3];
            *(float4*)(cdst + q*4) = w;
        }
    }
}

// ---------------- K8: fused reinsertion MLP + in-block reduction — f32x2, ITILE=2 ----------------
__global__ __launch_bounds__(256, 1) void k_t2(const unsigned char* __restrict__ maskt,
                                               const float* __restrict__ w2, const float* __restrict__ b2,
                                               const float* __restrict__ w3, const float* __restrict__ b3) {
    __shared__ __align__(16) float W2[32*32];
    __shared__ __align__(8)  float B2[32];
    __shared__ float W3[32];
    __shared__ float rc0[32], rc1[32];
    __shared__ float cjs[N1*33];
    __shared__ ull   skw[8];
    __shared__ float ssw[8];
    __shared__ float B3;
    int b = blockIdx.y;
    int i0 = blockIdx.x * 2;
    int tid = threadIdx.x;
    int wid = tid >> 5, lane = tid & 31;
    {
        float4 v = ((const float4*)w2)[tid];
        int kk = tid >> 3, q = tid & 7;
        W2[kk*32 + q*4 + 0] = v.x; W2[kk*32 + q*4 + 1] = v.y;
        W2[kk*32 + q*4 + 2] = v.z; W2[kk*32 + q*4 + 3] = v.w;
    }
    if (tid < 32) { B2[tid] = b2[tid]; W3[tid] = w3[tid]; }
    if (tid == 0) B3 = b3[0];
    if (tid < 32)      rc0[tid]    = g_rc[(size_t)(b*N1 + i0)*32 + tid];
    else if (tid < 64) rc1[tid-32] = (i0+1 < N1) ? g_rc[(size_t)(b*N1 + i0 + 1)*32 + (tid-32)] : 0.f;
    {
        const float4* ccb = (const float4*)(g_cc + (size_t)b*N1*32);
        for (int l = tid; l < N1*8; l += 256) {
            int j = l >> 3, q = l & 7;
            float4 v = ccb[l];
            cjs[j*33 + q*4 + 0] = v.x; cjs[j*33 + q*4 + 1] = v.y;
            cjs[j*33 + q*4 + 2] = v.z; cjs[j*33 + q*4 + 3] = v.w;
        }
    }
    __syncthreads();

    ull bk = 0; float bs = 0.f;
    int j = tid;
    if (j < N1) {
        const ull* B2d = (const ull*)B2;
        const float* cj = cjs + j*33;
        ull acc0[16], acc1[16];
        #pragma unroll
        for (int q = 0; q < 16; q++) { acc0[q] = B2d[q]; acc1[q] = B2d[q]; }
        #pragma unroll 4
        for (int kk = 0; kk < 32; kk++) {
            float cjk = cj[kk];
            ull hh0 = pack2(fmaxf(rc0[kk] + cjk, 0.f));
            ull hh1 = pack2(fmaxf(rc1[kk] + cjk, 0.f));
            const ulonglong2* wr = (const ulonglong2*)(W2 + kk*32);
            #pragma unroll
            for (int q = 0; q < 8; q++) {
                ulonglong2 w = wr[q];
                acc0[2*q]   = ffma2(hh0, w.x, acc0[2*q]);
                acc0[2*q+1] = ffma2(hh0, w.y, acc0[2*q+1]);
                acc1[2*q]   = ffma2(hh1, w.x, acc1[2*q]);
                acc1[2*q+1] = ffma2(hh1, w.y, acc1[2*q+1]);
            }
        }
        {
            int i = i0;
            float o = B3;
            #pragma unroll
            for (int q = 0; q < 16; q++) {
                float lo, hi;
                unpack2(acc0[q], lo, hi);
                o += fmaxf(lo, 0.f) * W3[2*q] + fmaxf(hi, 0.f) * W3[2*q+1];
            }
            float t2v = maskt[((size_t)b*N1 + i)*N1 + j] ? NEGV : tanhf(o)*6.0f;
            unsigned int lin = (unsigned int)(i*N1 + j);
            unsigned int u = __float_as_uint(t2v);
            unsigned int ord = (u >> 31) ? ~u : (u | 0x80000000u);
            ull key = ((ull)ord << 32) | (0xFFFFFFFFu - lin);
            if (key > bk) bk = key;
            bs += __expf(t2v - 6.f);
        }
        if (i0 + 1 < N1) {
            int i = i0 + 1;
            float o = B3;
            #pragma unroll
            for (int q = 0; q < 16; q++) {
                float lo, hi;
                unpack2(acc1[q], lo, hi);
                o += fmaxf(lo, 0.f) * W3[2*q] + fmaxf(hi, 0.f) * W3[2*q+1];
            }
            float t2v = maskt[((size_t)b*N1 + i)*N1 + j] ? NEGV : tanhf(o)*6.0f;
            unsigned int lin = (unsigned int)(i*N1 + j);
            unsigned int u = __float_as_uint(t2v);
            unsigned int ord = (u >> 31) ? ~u : (u | 0x80000000u);
            ull key = ((ull)ord << 32) | (0xFFFFFFFFu - lin);
            if (key > bk) bk = key;
            bs += __expf(t2v - 6.f);
        }
    }
    #pragma unroll
    for (int off = 16; off > 0; off >>= 1) {
        ull ok = __shfl_xor_sync(0xFFFFFFFF, bk, off);
        float os = __shfl_xor_sync(0xFFFFFFFF, bs, off);
        if (ok > bk) bk = ok;
        bs += os;
    }
    if (lane == 0) { skw[wid] = bk; ssw[wid] = bs; }
    __syncthreads();
    if (tid == 0) {
        ull k = skw[0]; float s = ssw[0];
        #pragma unroll
        for (int w = 1; w < 8; w++) {
            if (skw[w] > k) k = skw[w];
            s += ssw[w];
        }
        g_pkey[b*NT2B + blockIdx.x] = k;
        g_psum[b*NT2B + blockIdx.x] = s;
    }
}

// ---------------- K9: final per-batch reduce (deterministic) ----------------
__global__ void k_red(float* __restrict__ out) {
    int b = threadIdx.x;
    if (b < BB) {
        ull bk = 0; float s = 0.f;
        for (int p = 0; p < NT2B; p++) {
            ull k = g_pkey[b*NT2B + p];
            if (k > bk) bk = k;
            s += g_psum[b*NT2B + p];
        }
        unsigned int ord = (unsigned int)(bk >> 32);
        unsigned int u = (ord & 0x80000000u) ? (ord ^ 0x80000000u) : ~ord;
        float vmax = __uint_as_float(u);
        unsigned int lin = 0xFFFFFFFFu - (unsigned int)(bk & 0xFFFFFFFFu);
        float ll2 = vmax - 6.f - __logf(s);
        out[b*3 + 0] = (float)g_a1[b];
        out[b*3 + 1] = (float)(lin / N1);
        out[b*3 + 2] = (float)(lin % N1);
        out[BB*3 + b] = g_ll1[b] + ll2;
    }
}

// ---------------- launch ----------------
extern "C" void kernel_launch(void* const* d_in, const int* in_sizes, int n_in,
                              void* d_out, int out_size) {
    const float* h_wave      = (const float*)d_in[0];
    const int*   solution    = (const int*)d_in[1];
    const float* selrec      = (const float*)d_in[2];
    const int*   pre_action  = (const int*)d_in[3];
    const unsigned char* mt  = (const unsigned char*)d_in[4];
    const float* Wn  = (const float*)d_in[5];
    const float* Wg  = (const float*)d_in[6];
    const float* rmWQ = (const float*)d_in[7];
    const float* rmWK = (const float*)d_in[8];
    const float* rw1 = (const float*)d_in[9];
    const float* rb1 = (const float*)d_in[10];
    const float* rw2 = (const float*)d_in[11];
    const float* rb2 = (const float*)d_in[12];
    const float* rw3 = (const float*)d_in[13];
    const float* rb3 = (const float*)d_in[14];
    const float* i1q = (const float*)d_in[15];
    const float* i1k = (const float*)d_in[16];
    const float* i2q = (const float*)d_in[17];
    const float* i2k = (const float*)d_in[18];
    const float* ew1 = (const float*)d_in[19];
    const float* eb1 = (const float*)d_in[20];
    const float* ew2 = (const float*)d_in[21];
    const float* eb2 = (const float*)d_in[22];
    const float* ew3 = (const float*)d_in[23];
    const float* eb3 = (const float*)d_in[24];
    float* out = (float*)d_out;

    k_prep_mmat<<<BB + 4*DD + BB, DD>>>(h_wave, Wg, rmWQ, rmWK, solution);
    k_hhat<<<MM/16, DD>>>(h_wave, Wn);
    {
        dim3 gg(134, 8);
        k_pgemm<<<gg, 128>>>();
    }
    k_t1a<<<1600, 256>>>();
    k_t1b<<<BB, 128>>>(selrec, pre_action, rw1, rb1, rw2, rb2, rw3, rb3);
    {
        dim3 gq(16, 8);
        k_qt<<<gq, 128>>>(i1q, i1k, i2q, i2k);
    }
    {
        dim3 gr(7, BB);
        k_rc<<<gr, 128>>>(solution, ew1, eb1);
    }
    {
        dim3 gt(NT2B, BB);
        k_t2<<<gt, 256>>>(mt, ew2, eb2, ew3, eb3);
    }
    k_red<<<1, 64>>>(out);
}

// round 17
// speedup vs baseline: 1.0220x; 1.0085x over previous
#include <cuda_runtime.h>

#define BB 64
#define N1 201
#define DD 128
#define HF 100
#define MM (BB*N1)          // 12864
#define NEGV -1e20f
#define NT2B 101            // t2 blocks per batch (ceil(201/2))

typedef unsigned long long ull;

// ---------------- scratch ----------------
__device__ __align__(16) float g_gv[BB*DD];
__device__ __align__(16) float g_hhat[MM*DD];        // 6.6 MB
__device__ __align__(16) float g_M[4*DD*DD];         // WQ_h @ WK_h^T (removal)
__device__ __align__(16) float g_proj[4*MM*DD];      // P = hhat @ M_h (26 MB)
__device__ __align__(16) float g_qt[16*BB*DD];       // folded qtilde vectors
__device__ __align__(16) float g_feat[BB*HF*8];      // removal compat features
__device__ __align__(16) int2  g_idx[BB*200];        // (ipre, ipost) per item
__device__ __align__(16) float g_rc[MM*32];
__device__ __align__(16) float g_cc[MM*32];
__device__ int   g_a1[BB];
__device__ float g_ll1[BB];
__device__ ull   g_pkey[BB*NT2B];
__device__ float g_psum[BB*NT2B];

// ---------------- f32x2 helpers ----------------
__device__ __forceinline__ ull ffma2(ull a, ull b, ull c) {
    ull d;
    asm("fma.rn.f32x2 %0, %1, %2, %3;" : "=l"(d) : "l"(a), "l"(b), "l"(c));
    return d;
}
__device__ __forceinline__ ull pack2(float x) {
    ull r;
    asm("mov.b64 %0, {%1, %2};" : "=l"(r) : "f"(x), "f"(x));
    return r;
}
__device__ __forceinline__ ull pack2v(float lo, float hi) {
    ull r;
    asm("mov.b64 %0, {%1, %2};" : "=l"(r) : "f"(lo), "f"(hi));
    return r;
}
__device__ __forceinline__ void unpack2(ull v, float& lo, float& hi) {
    asm("mov.b64 {%0, %1}, %2;" : "=f"(lo), "=f"(hi) : "l"(v));
}

// ---------------- K1: prep (0..63) + mmat (64..575) + idx (576..639) ----------------
__global__ __launch_bounds__(128) void k_prep_mmat(const float* __restrict__ hw,
                                                   const float* __restrict__ Wg,
                                                   const float* __restrict__ WQ,
                                                   const float* __restrict__ WK,
                                                   const int* __restrict__ sol_g) {
    int bid = blockIdx.x;
    int tid = threadIdx.x;
    if (bid < BB) {
        __shared__ float hm[DD];
        int b = bid;
        const float* p = hw + (size_t)b*N1*DD + tid;
        float m = -3.4e38f;
        for (int n = 0; n < N1; n++) m = fmaxf(m, p[n*DD]);
        hm[tid] = m;
        __syncthreads();
        float s = 0.f;
        for (int k = 0; k < DD; k++) s += hm[k] * Wg[k*DD + tid];
        g_gv[b*DD + tid] = s;
    } else if (bid < BB + 4*DD) {
        __shared__ float wk[DD];
        int x = bid - BB;
        int h = x >> 7, dp = x & 127;
        wk[tid] = WK[(size_t)(h*DD + dp)*DD + tid];
        __syncthreads();
        const float4* q4 = (const float4*)(WQ + (size_t)(h*DD + tid)*DD);
        const float4* k4 = (const float4*)wk;
        float s = 0.f;
        #pragma unroll
        for (int c = 0; c < 32; c++) {
            float4 a = q4[c], bq = k4[c];
            s += a.x*bq.x + a.y*bq.y + a.z*bq.z + a.w*bq.w;
        }
        g_M[(size_t)(h*DD + tid)*DD + dp] = s;
    } else {
        __shared__ int sol[N1], inv[N1];
        int b = bid - (BB + 4*DD);
        for (int i = tid; i < N1; i += 128) sol[i] = sol_g[b*N1 + i];
        __syncthreads();
        for (int i = tid; i < N1; i += 128) inv[sol[i]] = i;
        __syncthreads();
        for (int item = tid; item < 200; item += 128) {
            int n = item + 1;
            g_idx[b*200 + item] = make_int2(inv[n], sol[sol[n]]);
        }
    }
}

// ---------------- K2: h_hat = h_wave @ Wn + g[b] — f32x2, 16 rows/block ----------------
__global__ __launch_bounds__(128) void k_hhat(const float* __restrict__ hw,
                                              const float* __restrict__ Wn) {
    __shared__ float Asf[DD][18];
    int r0 = blockIdx.x * 16;
    int tid = threadIdx.x;
    #pragma unroll
    for (int rr = 0; rr < 16; rr++) {
        Asf[tid][(rr & 7)*2 + (rr >> 3)] = hw[(size_t)(r0+rr)*DD + tid];
    }
    __syncthreads();
    ull acc[8];
    #pragma unroll
    for (int p = 0; p < 8; p++) {
        int bl = (r0 + p) / N1, bh = (r0 + p + 8) / N1;
        acc[p] = pack2v(g_gv[bl*DD + tid], g_gv[bh*DD + tid]);
    }
    #pragma unroll 4
    for (int k = 0; k < DD; k++) {
        ull w2 = pack2(Wn[k*DD + tid]);
        const ull* arow = (const ull*)&Asf[k][0];
        #pragma unroll
        for (int p = 0; p < 8; p++) acc[p] = ffma2(arow[p], w2, acc[p]);
    }
    #pragma unroll
    for (int p = 0; p < 8; p++) {
        float lo, hi; unpack2(acc[p], lo, hi);
        g_hhat[(size_t)(r0+p)*DD + tid]   = lo;
        g_hhat[(size_t)(r0+p+8)*DD + tid] = hi;
    }
}

// ---------------- K4: P = hhat @ M — f32x2, 96x64 tile, B-resident + A double-buffer ----------------
__global__ __launch_bounds__(128) void k_pgemm() {
    __shared__ __align__(16) float Bs[DD][64];        // full 128x64 W slice: 32 KB
    __shared__ __align__(16) float As[2][16][98];     // A chunk double buffer
    int bm = blockIdx.x;              // 0..133 (134*96 = 12864 exact)
    int bn = blockIdx.y;              // 0..7
    int h  = bn >> 1;
    int d0 = (bn & 1) * 64;
    const float* W = g_M + (size_t)h * DD * DD;

    int tid = threadIdx.x;
    int tx = tid & 15, ty = tid >> 4;

    for (int l = tid; l < 2048; l += 128) {
        int row = l >> 4, c4 = (l & 15) * 4;
        *(float4*)&Bs[row][c4] = *(const float4*)(W + (size_t)row*DD + d0 + c4);
    }

    int arowv[3], ac4v[3];
    #pragma unroll
    for (int q = 0; q < 3; q++) {
        int idx = tid + 128*q;
        arowv[q] = idx >> 2;
        ac4v[q]  = (idx & 3) * 4;
    }

    float4 aR[3];
    #pragma unroll
    for (int q = 0; q < 3; q++)
        aR[q] = *(const float4*)(g_hhat + (size_t)(bm*96 + arowv[q])*DD + 0 + ac4v[q]);
    #pragma unroll
    for (int q = 0; q < 3; q++) {
        As[0][ac4v[q]+0][arowv[q]] = aR[q].x; As[0][ac4v[q]+1][arowv[q]] = aR[q].y;
        As[0][ac4v[q]+2][arowv[q]] = aR[q].z; As[0][ac4v[q]+3][arowv[q]] = aR[q].w;
    }
    __syncthreads();

    ull c2[6][4] = {};
    #pragma unroll 1
    for (int ch = 0; ch < 8; ch++) {
        int buf = ch & 1;
        if (ch < 7) {
            #pragma unroll
            for (int q = 0; q < 3; q++)
                aR[q] = *(const float4*)(g_hhat + (size_t)(bm*96 + arowv[q])*DD + (ch+1)*16 + ac4v[q]);
        }
        #pragma unroll
        for (int kk = 0; kk < 16; kk++) {
            const ull* ap = (const ull*)&As[buf][kk][ty*12];
            float4 bv = *(const float4*)&Bs[ch*16 + kk][tx*4];
            ull b0 = pack2(bv.x), b1 = pack2(bv.y), b2 = pack2(bv.z), b3 = pack2(bv.w);
            #pragma unroll
            for (int p = 0; p < 6; p++) {
                ull a2 = ap[p];
                c2[p][0] = ffma2(a2, b0, c2[p][0]);
                c2[p][1] = ffma2(a2, b1, c2[p][1]);
                c2[p][2] = ffma2(a2, b2, c2[p][2]);
                c2[p][3] = ffma2(a2, b3, c2[p][3]);
            }
        }
        if (ch < 7) {
            #pragma unroll
            for (int q = 0; q < 3; q++) {
                As[buf^1][ac4v[q]+0][arowv[q]] = aR[q].x; As[buf^1][ac4v[q]+1][arowv[q]] = aR[q].y;
                As[buf^1][ac4v[q]+2][arowv[q]] = aR[q].z; As[buf^1][ac4v[q]+3][arowv[q]] = aR[q].w;
            }
        }
        __syncthreads();
    }

    float* out = g_proj + (size_t)h * MM * DD;
    int row0 = bm*96 + ty*12, col0 = d0 + tx*4;
    #pragma unroll
    for (int p = 0; p < 6; p++) {
        float l0,h0,l1,h1,l2,h2,l3,h3;
        unpack2(c2[p][0], l0, h0); unpack2(c2[p][1], l1, h1);
        unpack2(c2[p][2], l2, h2); unpack2(c2[p][3], l3, h3);
        float4 v0; v0.x=l0; v0.y=l1; v0.z=l2; v0.w=l3;
        float4 v1; v1.x=h0; v1.y=h1; v1.z=h2; v1.w=h3;
        *(float4*)(out + (size_t)(row0 + 2*p + 0)*DD + col0) = v0;
        *(float4*)(out + (size_t)(row0 + 2*p + 1)*DD + col0) = v1;
    }
}

// ---------------- K5a: removal compat dots — warp-per-item, no smem ----------------
__global__ __launch_bounds__(256) void k_t1a() {
    int w = blockIdx.x * 8 + (threadIdx.x >> 5);   // 0..12799
    int lane = threadIdx.x & 31;
    int b = w / 200, item = w % 200;
    int2 ix = g_idx[b*200 + item];
    int n = item + 1;
    int half = (item < HF) ? 0 : 1;
    int m = (item < HF) ? item : (item - HF);

    float4 xn = ((const float4*)(g_hhat + (size_t)(b*N1 + n   )*DD))[lane];
    float4 xp = ((const float4*)(g_hhat + (size_t)(b*N1 + ix.y)*DD))[lane];
    float4 pp4[4], pn4[4];
    #pragma unroll
    for (int h = 0; h < 4; h++) {
        pp4[h] = ((const float4*)(g_proj + ((size_t)h*MM + b*N1 + ix.x)*DD))[lane];
        pn4[h] = ((const float4*)(g_proj + ((size_t)h*MM + b*N1 + n   )*DD))[lane];
    }
    float sh[4];
    #pragma unroll
    for (int h = 0; h < 4; h++) {
        float4 pp = pp4[h], pn = pn4[h];
        float s = pp.x*xn.x + pp.y*xn.y + pp.z*xn.z + pp.w*xn.w
                + pn.x*xp.x + pn.y*xp.y + pn.z*xp.z + pn.w*xp.w
                - (pp.x*xp.x + pp.y*xp.y + pp.z*xp.z + pp.w*xp.w);
        #pragma unroll
        for (int off = 16; off > 0; off >>= 1) s += __shfl_xor_sync(0xFFFFFFFF, s, off);
        sh[h] = s;
    }
    if (lane == 0) {
        float4 v; v.x = sh[0]; v.y = sh[1]; v.z = sh[2]; v.w = sh[3];
        *(float4*)(g_feat + ((size_t)b*HF + m)*8 + half*4) = v;
    }
}

// ---------------- K5b: removal MLP + softmax/argmax ----------------
__global__ __launch_bounds__(128) void k_t1b(const float* __restrict__ selrec,
                     const int* __restrict__ pre_action,
                     const float* __restrict__ w1, const float* __restrict__ b1,
                     const float* __restrict__ w2, const float* __restrict__ b2,
                     const float* __restrict__ w3, const float* __restrict__ b3) {
    __shared__ float t1s[HF];
    __shared__ float W1[12*32], B1[32], W2s[32*32], B2s[32], W3s[32];
    int b = blockIdx.x, tid = threadIdx.x;
    for (int i = tid; i < 12*32; i += 128) W1[i] = w1[i];
    for (int i = tid; i < 32*32; i += 128) W2s[i] = w2[i];
    if (tid < 32) { B1[tid] = b1[tid]; B2s[tid] = b2[tid]; W3s[tid] = w3[tid]; }
    __syncthreads();

    if (tid < HF) {
        int m = tid;
        float feat[12];
        #pragma unroll
        for (int c = 0; c < 8; c++) feat[c] = g_feat[((size_t)b*HF + m)*8 + c];
        #pragma unroll
        for (int s = 0; s < 4; s++) feat[8+s] = selrec[b*4*HF + s*HF + m];
        float h1[32];
        #pragma unroll
        for (int c = 0; c < 32; c++) {
            float s = B1[c];
            #pragma unroll
            for (int f = 0; f < 12; f++) s += feat[f] * W1[f*32 + c];
            h1[c] = fmaxf(s, 0.f);
        }
        float h2[32];
        #pragma unroll
        for (int c = 0; c < 32; c++) {
            float s = B2s[c];
            #pragma unroll
            for (int f = 0; f < 32; f++) s += h1[f] * W2s[f*32 + c];
            h2[c] = fmaxf(s, 0.f);
        }
        float o = b3[0];
        #pragma unroll
        for (int c = 0; c < 32; c++) o += h2[c] * W3s[c];
        float t1 = tanhf(o) * 6.0f;
        if (pre_action[0] > 0 && m == pre_action[b*2]) t1 = NEGV;
        t1s[m] = t1;
    }
    __syncthreads();
    if (tid == 0) {
        float mx = t1s[0]; int am = 0;
        for (int m = 1; m < HF; m++) if (t1s[m] > mx) { mx = t1s[m]; am = m; }
        float se = 0.f;
        for (int m = 0; m < HF; m++) se += __expf(t1s[m] - mx);
        g_a1[b] = am;
        g_ll1[b] = -__logf(se);
    }
}

// ---------------- K6: qtilde — weights amortized over 4 batches, grid (16,16) ----------------
__global__ __launch_bounds__(128) void k_qt(const float* __restrict__ i1q, const float* __restrict__ i1k,
                                            const float* __restrict__ i2q, const float* __restrict__ i2k) {
    __shared__ float hp[4][DD];
    __shared__ float u[4][DD];
    __shared__ float Ws[16][DD+2];
    int x = blockIdx.x;               // 0..15: t*4+h
    int t = x >> 2, h = x & 3;
    int b0 = blockIdx.y * 4;
    int tid = threadIdx.x;
    const float* Wq = ((t & 1) ? i2q : i1q) + (size_t)h*DD*DD;
    const float* Wk = ((t & 1) ? i2k : i1k) + (size_t)h*DD*DD;

    #pragma unroll
    for (int bb = 0; bb < 4; bb++) {
        int b = b0 + bb;
        int a1 = g_a1[b];
        int pos = (t < 2) ? (1 + a1) : (1 + HF + a1);
        hp[bb][tid] = g_hhat[(size_t)(b*N1 + pos)*DD + tid];
    }
    __syncthreads();
    {
        float acc[4] = {};
        for (int k = 0; k < DD; k++) {
            float w = Wq[(size_t)k*DD + tid];
            #pragma unroll
            for (int bb = 0; bb < 4; bb++) acc[bb] += hp[bb][k] * w;
        }
        #pragma unroll
        for (int bb = 0; bb < 4; bb++) u[bb][tid] = acc[bb];
    }
    __syncthreads();
    float q[4] = {};
    for (int e0 = 0; e0 < DD; e0 += 16) {
        #pragma unroll
        for (int qq = 0; qq < 16; qq++) {
            int l = tid + 128*qq;
            int dd = l >> 4, ee = l & 15;
            Ws[ee][dd] = Wk[(size_t)dd*DD + e0 + ee];
        }
        __syncthreads();
        #pragma unroll
        for (int ee = 0; ee < 16; ee++) {
            float w = Ws[ee][tid];
            #pragma unroll
            for (int bb = 0; bb < 4; bb++) q[bb] += u[bb][e0+ee] * w;
        }
        __syncthreads();
    }
    #pragma unroll
    for (int bb = 0; bb < 4; bb++)
        g_qt[((size_t)x*BB + b0 + bb)*DD + tid] = q[bb];
}

// ---------------- K7: row/col layer-1 — smem-staged, coalesced ----------------
__global__ __launch_bounds__(128) void k_rc(const int* __restrict__ sol_g,
                                            const float* __restrict__ w1, const float* __restrict__ b1v) {
    __shared__ __align__(16) float qv[16*DD];        // 8 KB
    __shared__ __align__(16) float xi[32][132];
    __shared__ __align__(16) float xs[32][132];
    __shared__ float sdots[32][17];
    __shared__ float W1[16*32], B1[32];
    __shared__ int   soli[32];
    int b = blockIdx.y;
    int i0 = blockIdx.x * 32;        // 7*32 = 224 >= 201
    int tid = threadIdx.x;
    int wid = tid >> 5, lane = tid & 31;

    {
        const float4* src = (const float4*)(g_qt);
        float4* dst = (float4*)qv;
        for (int l = tid; l < 16*DD/4; l += 128) {
            int x = l >> 5, q = l & 31;
            dst[l] = src[((size_t)x*BB + b)*32 + q];
        }
    }
    for (int l = tid; l < 16*32; l += 128) W1[l] = w1[l];
    if (tid < 32) B1[tid] = b1v[tid];
    if (tid < 32) soli[tid] = (i0 + tid < N1) ? sol_g[b*N1 + i0 + tid] : 0;
    __syncthreads();

    {
        const float4* src = (const float4*)(g_hhat + (size_t)(b*N1 + i0)*DD);
        int nrows = min(32, N1 - i0);
        for (int l = tid; l < nrows*32; l += 128) {
            int row = l >> 5, c = l & 31;
            float4 v = src[(size_t)row*32 + c];
            *(float4*)&xi[row][c*4] = v;
        }
    }
    for (int row = wid; row < 32; row += 4) {
        if (i0 + row < N1) {
            const float4* src = (const float4*)(g_hhat + (size_t)(b*N1 + soli[row])*DD);
            *(float4*)&xs[row][lane*4] = src[lane];
        }
    }
    __syncthreads();

    int il = tid & 31, h = tid >> 5;
    float s0 = 0.f, s1 = 0.f, s2 = 0.f, s3 = 0.f;
    {
        const float4* q0 = (const float4*)(qv + (0*4+h)*DD);
        const float4* q1 = (const float4*)(qv + (1*4+h)*DD);
        const float4* q2 = (const float4*)(qv + (2*4+h)*DD);
        const float4* q3 = (const float4*)(qv + (3*4+h)*DD);
        #pragma unroll 8
        for (int c = 0; c < 32; c++) {
            float4 vi = *(const float4*)&xi[il][c*4];
            float4 vs = *(const float4*)&xs[il][c*4];
            float4 a0 = q0[c], a1 = q1[c], a2 = q2[c], a3 = q3[c];
            s0 += a0.x*vi.x + a0.y*vi.y + a0.z*vi.z + a0.w*vi.w;
            s1 += a1.x*vs.x + a1.y*vs.y + a1.z*vs.z + a1.w*vs.w;
            s2 += a2.x*vi.x + a2.y*vi.y + a2.z*vi.z + a2.w*vi.w;
            s3 += a3.x*vs.x + a3.y*vs.y + a3.z*vs.z + a3.w*vs.w;
        }
    }
    const float invs = 0.08838834764831845f;  // 1/sqrt(128)
    sdots[il][h]      = s0*invs;
    sdots[il][4+h]    = s1*invs;
    sdots[il][8+h]    = s2*invs;
    sdots[il][12+h]   = s3*invs;
    __syncthreads();

    int cg = tid >> 5;
    int i = i0 + il;
    if (i < N1) {
        float f[16];
        #pragma unroll
        for (int k = 0; k < 16; k++) f[k] = sdots[il][k];
        float rs[8], cs[8];
        #pragma unroll
        for (int cc = 0; cc < 8; cc++) {
            int c = cg*8 + cc;
            float r = 0.f, s = B1[c];
            #pragma unroll
            for (int k = 0; k < 8; k++) {
                r += f[k]     * W1[k*32 + c];
                s += f[8+k]   * W1[(8+k)*32 + c];
            }
            rs[cc] = r; cs[cc] = s;
        }
        float* rdst = g_rc + (size_t)(b*N1 + i)*32 + cg*8;
        float* cdst = g_cc + (size_t)(b*N1 + i)*32 + cg*8;
        #pragma unroll
        for (int q = 0; q < 2; q++) {
            float4 v; v.x = rs[q*4]; v.y = rs[q*4+1]; v.z = rs[q*4+2]; v.w = rs[q*4+3];
            *(float4*)(rdst + q*4) = v;
            float4 w; w.x = cs[q*4]; w.y = cs[q*4+1]; w.z = cs[q*4+2]; w.w = cs[q*4+3];
            *(float4*)(cdst + q*4) = w;
        }
    }
}

// ---------------- K8: fused reinsertion MLP + in-block reduction — f32x2, ITILE=2 ----------------
__global__ __launch_bounds__(256, 1) void k_t2(const unsigned char* __restrict__ maskt,
                                               const float* __restrict__ w2, const float* __restrict__ b2,
                                               const float* __restrict__ w3, const float* __restrict__ b3) {
    __shared__ __align__(16) float W2[32*32];
    __shared__ __align__(8)  float B2[32];
    __shared__ float W3[32];
    __shared__ float rc0[32], rc1[32];
    __shared__ float cjs[N1*33];
    __shared__ ull   skw[8];
    __shared__ float ssw[8];
    __shared__ float B3;
    int b = blockIdx.y;
    int i0 = blockIdx.x * 2;
    int tid = threadIdx.x;
    int wid = tid >> 5, lane = tid & 31;
    {
        float4 v = ((const float4*)w2)[tid];
        int kk = tid >> 3, q = tid & 7;
        W2[kk*32 + q*4 + 0] = v.x; W2[kk*32 + q*4 + 1] = v.y;
        W2[kk*32 + q*4 + 2] = v.z; W2[kk*32 + q*4 + 3] = v.w;
    }
    if (tid < 32) { B2[tid] = b2[tid]; W3[tid] = w3[tid]; }
    if (tid == 0) B3 = b3[0];
    if (tid < 32)      rc0[tid]    = g_rc[(size_t)(b*N1 + i0)*32 + tid];
    else if (tid < 64) rc1[tid-32] = (i0+1 < N1) ? g_rc[(size_t)(b*N1 + i0 + 1)*32 + (tid-32)] : 0.f;
    {
        const float4* ccb = (const float4*)(g_cc + (size_t)b*N1*32);
        for (int l = tid; l < N1*8; l += 256) {
            int j = l >> 3, q = l & 7;
            float4 v = ccb[l];
            cjs[j*33 + q*4 + 0] = v.x; cjs[j*33 + q*4 + 1] = v.y;
            cjs[j*33 + q*4 + 2] = v.z; cjs[j*33 + q*4 + 3] = v.w;
        }
    }
    __syncthreads();

    ull bk = 0; float bs = 0.f;
    int j = tid;
    if (j < N1) {
        const ull* B2d = (const ull*)B2;
        const float* cj = cjs + j*33;
        ull acc0[16], acc1[16];
        #pragma unroll
        for (int q = 0; q < 16; q++) { acc0[q] = B2d[q]; acc1[q] = B2d[q]; }
        #pragma unroll 4
        for (int kk = 0; kk < 32; kk++) {
            float cjk = cj[kk];
            ull hh0 = pack2(fmaxf(rc0[kk] + cjk, 0.f));
            ull hh1 = pack2(fmaxf(rc1[kk] + cjk, 0.f));
            const ulonglong2* wr = (const ulonglong2*)(W2 + kk*32);
            #pragma unroll
            for (int q = 0; q < 8; q++) {
                ulonglong2 w = wr[q];
                acc0[2*q]   = ffma2(hh0, w.x, acc0[2*q]);
                acc0[2*q+1] = ffma2(hh0, w.y, acc0[2*q+1]);
                acc1[2*q]   = ffma2(hh1, w.x, acc1[2*q]);
                acc1[2*q+1] = ffma2(hh1, w.y, acc1[2*q+1]);
            }
        }
        {
            int i = i0;
            float o = B3;
            #pragma unroll
            for (int q = 0; q < 16; q++) {
                float lo, hi;
                unpack2(acc0[q], lo, hi);
                o += fmaxf(lo, 0.f) * W3[2*q] + fmaxf(hi, 0.f) * W3[2*q+1];
            }
            float t2v = maskt[((size_t)b*N1 + i)*N1 + j] ? NEGV : tanhf(o)*6.0f;
            unsigned int lin = (unsigned int)(i*N1 + j);
            unsigned int u = __float_as_uint(t2v);
            unsigned int ord = (u >> 31) ? ~u : (u | 0x80000000u);
            ull key = ((ull)ord << 32) | (0xFFFFFFFFu - lin);
            if (key > bk) bk = key;
            bs += __expf(t2v - 6.f);
        }
        if (i0 + 1 < N1) {
            int i = i0 + 1;
            float o = B3;
            #pragma unroll
            for (int q = 0; q < 16; q++) {
                float lo, hi;
                unpack2(acc1[q], lo, hi);
                o += fmaxf(lo, 0.f) * W3[2*q] + fmaxf(hi, 0.f) * W3[2*q+1];
            }
            float t2v = maskt[((size_t)b*N1 + i)*N1 + j] ? NEGV : tanhf(o)*6.0f;
            unsigned int lin = (unsigned int)(i*N1 + j);
            unsigned int u = __float_as_uint(t2v);
            unsigned int ord = (u >> 31) ? ~u : (u | 0x80000000u);
            ull key = ((ull)ord << 32) | (0xFFFFFFFFu - lin);
            if (key > bk) bk = key;
            bs += __expf(t2v - 6.f);
        }
    }
    #pragma unroll
    for (int off = 16; off > 0; off >>= 1) {
        ull ok = __shfl_xor_sync(0xFFFFFFFF, bk, off);
        float os = __shfl_xor_sync(0xFFFFFFFF, bs, off);
        if (ok > bk) bk = ok;
        bs += os;
    }
    if (lane == 0) { skw[wid] = bk; ssw[wid] = bs; }
    __syncthreads();
    if (tid == 0) {
        ull k = skw[0]; float s = ssw[0];
        #pragma unroll
        for (int w = 1; w < 8; w++) {
            if (skw[w] > k) k = skw[w];
            s += ssw[w];
        }
        g_pkey[b*NT2B + blockIdx.x] = k;
        g_psum[b*NT2B + blockIdx.x] = s;
    }
}

// ---------------- K9: final per-batch reduce (deterministic) ----------------
__global__ void k_red(float* __restrict__ out) {
    int b = threadIdx.x;
    if (b < BB) {
        ull bk = 0; float s = 0.f;
        for (int p = 0; p < NT2B; p++) {
            ull k = g_pkey[b*NT2B + p];
            if (k > bk) bk = k;
            s += g_psum[b*NT2B + p];
        }
        unsigned int ord = (unsigned int)(bk >> 32);
        unsigned int u = (ord & 0x80000000u) ? (ord ^ 0x80000000u) : ~ord;
        float vmax = __uint_as_float(u);
        unsigned int lin = 0xFFFFFFFFu - (unsigned int)(bk & 0xFFFFFFFFu);
        float ll2 = vmax - 6.f - __logf(s);
        out[b*3 + 0] = (float)g_a1[b];
        out[b*3 + 1] = (float)(lin / N1);
        out[b*3 + 2] = (float)(lin % N1);
        out[BB*3 + b] = g_ll1[b] + ll2;
    }
}

// ---------------- launch ----------------
extern "C" void kernel_launch(void* const* d_in, const int* in_sizes, int n_in,
                              void* d_out, int out_size) {
    const float* h_wave      = (const float*)d_in[0];
    const int*   solution    = (const int*)d_in[1];
    const float* selrec      = (const float*)d_in[2];
    const int*   pre_action  = (const int*)d_in[3];
    const unsigned char* mt  = (const unsigned char*)d_in[4];
    const float* Wn  = (const float*)d_in[5];
    const float* Wg  = (const float*)d_in[6];
    const float* rmWQ = (const float*)d_in[7];
    const float* rmWK = (const float*)d_in[8];
    const float* rw1 = (const float*)d_in[9];
    const float* rb1 = (const float*)d_in[10];
    const float* rw2 = (const float*)d_in[11];
    const float* rb2 = (const float*)d_in[12];
    const float* rw3 = (const float*)d_in[13];
    const float* rb3 = (const float*)d_in[14];
    const float* i1q = (const float*)d_in[15];
    const float* i1k = (const float*)d_in[16];
    const float* i2q = (const float*)d_in[17];
    const float* i2k = (const float*)d_in[18];
    const float* ew1 = (const float*)d_in[19];
    const float* eb1 = (const float*)d_in[20];
    const float* ew2 = (const float*)d_in[21];
    const float* eb2 = (const float*)d_in[22];
    const float* ew3 = (const float*)d_in[23];
    const float* eb3 = (const float*)d_in[24];
    float* out = (float*)d_out;

    k_prep_mmat<<<BB + 4*DD + BB, DD>>>(h_wave, Wg, rmWQ, rmWK, solution);
    k_hhat<<<MM/16, DD>>>(h_wave, Wn);
    {
        dim3 gg(134, 8);
        k_pgemm<<<gg, 128>>>();
    }
    k_t1a<<<1600, 256>>>();
    k_t1b<<<BB, 128>>>(selrec, pre_action, rw1, rb1, rw2, rb2, rw3, rb3);
    {
        dim3 gq(16, 16);
        k_qt<<<gq, 128>>>(i1q, i1k, i2q, i2k);
    }
    {
        dim3 gr(7, BB);
        k_rc<<<gr, 128>>>(solution, ew1, eb1);
    }
    {
        dim3 gt(NT2B, BB);
        k_t2<<<gt, 256>>>(mt, ew2, eb2, ew3, eb3);
    }
    k_red<<<1, 64>>>(out);
}